// round 11
// baseline (speedup 1.0000x reference)
#include <cuda_runtime.h>
#include <cuda_fp16.h>
#include <cfloat>
#include <math.h>

// VectorQuantizer R11: HFMA2 (fp16x2, rt=2) filter GEMM + lossless candidate
// pruning + exact fp32 rescore (idx bit-identical to R2/R10) + fused gather.
// x:[65536,256] f32, cb:[1024,256] f32.
// out: [ y (N*D) | idx as float (N) | loss | perplexity | usage | H ]

#define N_FIXED 65536
#define D 256
#define KCB 1024
#define BN 64
#define NT 128
#define CAP 24
#define TAU 6e-3f
#define INVSC2 0.001953125f   // 2/1024

// smem byte offsets
#define XS_H  0               // 64 x 264 fp16           = 33792
#define CS_O  33792           // 2 x 32 x 136 fp16       = 17408
#define E2_O  51200           // 1024 f32                = 4096
#define X2_O  55296           // 64 f32
#define RMN_O 55552           // 64 u32
#define CNT_O 55808           // 64 i32
#define CK_O  56064           // 64 x 24 u16             = 3072
#define IDX_O 59136           // 64 i32
#define WS_O  59392           // 4 dbl
#define SMEM_B 59424

__device__ __half       g_cbh[KCB * D];
__device__ float        g_e2[KCB];
__device__ unsigned int g_counts[KCB];
__device__ double       g_partial[N_FIXED / BN];

// order-preserving float<->uint for atomicMin on signed floats
__device__ __forceinline__ unsigned fordu(float f) {
    unsigned b = __float_as_uint(f);
    return b ^ (unsigned)(((int)b >> 31) | 0x80000000);
}
__device__ __forceinline__ float finvu(unsigned u) {
    unsigned b = u ^ ((u & 0x80000000u) ? 0x80000000u : 0xFFFFFFFFu);
    return __uint_as_float(b);
}

// exact sequential fp32 dot, d ascending (matches R2 per-code chain)
__device__ __forceinline__ float seqdot256(const float* __restrict__ xr,
                                           const float* __restrict__ cr) {
    float s = 0.0f;
#pragma unroll 16
    for (int d = 0; d < 256; ++d)
        s = fmaf(__ldg(xr + d), __ldg(cr + d), s);
    return s;
}

__global__ void vq_init_kernel() {
    int t = threadIdx.x;
    if (t < KCB) g_counts[t] = 0u;
}

// e2[k] (exact chain) + fp16 codebook scaled by 1024 (exact pow2)
__global__ void vq_prep_kernel(const float* __restrict__ cb) {
    int row  = blockIdx.x * 8 + (threadIdx.x >> 5);
    int lane = threadIdx.x & 31;
    float s = 0.0f;
#pragma unroll
    for (int j = 0; j < 8; ++j) {
        int   d = lane + j * 32;
        float v = cb[row * D + d];
        g_cbh[row * D + d] = __float2half_rn(v * 1024.0f);
        s = fmaf(v, v, s);
    }
#pragma unroll
    for (int m = 16; m >= 1; m >>= 1)
        s += __shfl_xor_sync(0xffffffffu, s, m);
    if (lane == 0) g_e2[row] = s;
}

// ---------------------------------------------------------------------------
// Fused: HFMA2 filter GEMM (64 rows x 1024 codes) + candidate collect +
// exact rescore + gather/histogram/SSE. 128 threads, 3 CTAs/SM.
// ---------------------------------------------------------------------------
__global__ void __launch_bounds__(NT, 3)
vq_main_kernel(const float* __restrict__ x, const float* __restrict__ cb,
               float* __restrict__ y_out, float* __restrict__ idxf_out) {
    extern __shared__ char smem[];
    __half*         xs   = (__half*)(smem + XS_H);
    __half*         cs   = (__half*)(smem + CS_O);
    float*          e2s  = (float*)(smem + E2_O);
    float*          x2s  = (float*)(smem + X2_O);
    unsigned*       rmn  = (unsigned*)(smem + RMN_O);
    int*            cnt  = (int*)(smem + CNT_O);
    unsigned short* ck   = (unsigned short*)(smem + CK_O);
    int*            idxs = (int*)(smem + IDX_O);
    double*         wsum = (double*)(smem + WS_O);

    const int tid = threadIdx.x;
    const int tx  = tid & 15;
    const int ty  = tid >> 4;
    const int n0  = blockIdx.x * BN;

    for (int i = tid; i < KCB; i += NT) e2s[i] = g_e2[i];
    if (tid < BN) { rmn[tid] = 0xFFFFFFFFu; cnt[tid] = 0; }

    // x tile fp32 -> fp16 smem (row stride 264 halves)
    const float4* __restrict__ x4 = (const float4*)x;
#pragma unroll
    for (int u = 0; u < 32; ++u) {
        int f  = tid + u * NT;
        int r  = f >> 6;
        int d4 = f & 63;
        float4 v = __ldg(&x4[(size_t)(n0 + r) * 64 + d4]);
        __half2* dst = (__half2*)(xs + r * 264 + d4 * 4);
        dst[0] = __floats2half2_rn(v.x, v.y);
        dst[1] = __floats2half2_rn(v.z, v.w);
    }

    // x2 per row (EXACT R2 chain: lane tx sums float4 idx tx*4+q, butterfly)
#pragma unroll
    for (int i = 0; i < 8; ++i) {
        int r = ty * 8 + i;
        float s = 0.0f;
#pragma unroll
        for (int q = 0; q < 4; ++q) {
            float4 v = __ldg(&x4[(size_t)(n0 + r) * 64 + tx * 4 + q]);
            s = fmaf(v.x, v.x, s);
            s = fmaf(v.y, v.y, s);
            s = fmaf(v.z, v.z, s);
            s = fmaf(v.w, v.w, s);
        }
#pragma unroll
        for (int m = 8; m >= 1; m >>= 1)
            s += __shfl_xor_sync(0xffffffffu, s, m, 16);
        if (tx == 0) x2s[r] = s;
    }

    // preload code chunk 0 (kt=0,dt=0) transposed [dd][k]
    {
#pragma unroll
        for (int u = 0; u < 4; ++u) {
            int f = tid + u * NT;          // 0..511
            int k = f >> 2, sg = f & 3;
            uint4 v = *(const uint4*)(g_cbh + (size_t)k * D + sg * 8);
            const unsigned short* ps = (const unsigned short*)&v;
#pragma unroll
            for (int j = 0; j < 8; ++j)
                ((unsigned short*)cs)[(sg * 8 + j) * 136 + k] = ps[j];
        }
    }
    __syncthreads();

    __half2 simp[8][4];

#pragma unroll 1
    for (int cc = 0; cc < 64; ++cc) {      // kt = cc>>3, dt = cc&7
        const int kt = cc >> 3;
        const int dt = cc & 7;

        if (dt == 0) {
            const __half2 z = __floats2half2_rn(0.0f, 0.0f);
#pragma unroll
            for (int i = 0; i < 8; ++i)
#pragma unroll
                for (int j = 0; j < 4; ++j) simp[i][j] = z;
        }

        // prefetch next chunk into registers
        uint4 pv[4];
        const bool hn = (cc < 63);
        if (hn) {
            int nkt = (cc + 1) >> 3, ndt = (cc + 1) & 7;
#pragma unroll
            for (int u = 0; u < 4; ++u) {
                int f = tid + u * NT;
                int k = f >> 2, sg = f & 3;
                pv[u] = *(const uint4*)(g_cbh + (size_t)(nkt * 128 + k) * D
                                        + ndt * 32 + sg * 8);
            }
        }

        const __half* cbuf = cs + (cc & 1) * (32 * 136);
#pragma unroll
        for (int dd8 = 0; dd8 < 4; ++dd8) {
            uint4 xh[8];
#pragma unroll
            for (int i = 0; i < 8; ++i)
                xh[i] = *(const uint4*)(xs + (ty * 8 + i) * 264
                                        + dt * 32 + dd8 * 8);
#pragma unroll
            for (int j = 0; j < 8; ++j) {
                uint4 cw = *(const uint4*)(cbuf + (dd8 * 8 + j) * 136 + tx * 8);
                __half2 c0 = *(__half2*)&cw.x;
                __half2 c1 = *(__half2*)&cw.y;
                __half2 c2 = *(__half2*)&cw.z;
                __half2 c3 = *(__half2*)&cw.w;
                const unsigned sel = (j & 1) ? 0x3232u : 0x1010u;
#pragma unroll
                for (int i = 0; i < 8; ++i) {
                    unsigned w  = ((const unsigned*)&xh[i])[j >> 1];
                    unsigned bb = __byte_perm(w, w, sel);
                    __half2 xb = *(__half2*)&bb;
                    simp[i][0] = __hfma2(xb, c0, simp[i][0]);
                    simp[i][1] = __hfma2(xb, c1, simp[i][1]);
                    simp[i][2] = __hfma2(xb, c2, simp[i][2]);
                    simp[i][3] = __hfma2(xb, c3, simp[i][3]);
                }
            }
        }

        // store prefetched chunk to the other buffer
        if (hn) {
            __half* dst = cs + ((cc + 1) & 1) * (32 * 136);
#pragma unroll
            for (int u = 0; u < 4; ++u) {
                int f = tid + u * NT;
                int k = f >> 2, sg = f & 3;
                const unsigned short* ps = (const unsigned short*)&pv[u];
#pragma unroll
                for (int j = 0; j < 8; ++j)
                    ((unsigned short*)dst)[(sg * 8 + j) * 136 + k] = ps[j];
            }
        }

        // per-kt epilogue: scores, running row-min, candidate collect
        if (dt == 7) {
#pragma unroll
            for (int i = 0; i < 8; ++i) {
                int r = ty * 8 + i;
                float mn = FLT_MAX;
#pragma unroll
                for (int jp = 0; jp < 4; ++jp) {
                    float2 sf = __half22float2(simp[i][jp]);
                    int k0 = kt * 128 + tx * 8 + jp * 2;
                    float s0 = fmaf(sf.x, -INVSC2, e2s[k0]);
                    float s1 = fmaf(sf.y, -INVSC2, e2s[k0 + 1]);
                    mn = fminf(mn, fminf(s0, s1));
                }
#pragma unroll
                for (int m = 8; m >= 1; m >>= 1)
                    mn = fminf(mn, __shfl_xor_sync(0xffffffffu, mn, m, 16));
                if (tx == 0) atomicMin(&rmn[r], fordu(mn));
            }
            __syncthreads();
#pragma unroll
            for (int i = 0; i < 8; ++i) {
                int r = ty * 8 + i;
                float thr = finvu(rmn[r]) + TAU;
#pragma unroll
                for (int jp = 0; jp < 4; ++jp) {
                    float2 sf = __half22float2(simp[i][jp]);
                    int k0 = kt * 128 + tx * 8 + jp * 2;
                    float s0 = fmaf(sf.x, -INVSC2, e2s[k0]);
                    float s1 = fmaf(sf.y, -INVSC2, e2s[k0 + 1]);
                    if (s0 <= thr) {
                        int p = atomicAdd(&cnt[r], 1);
                        if (p < CAP) ck[r * CAP + p] = (unsigned short)k0;
                    }
                    if (s1 <= thr) {
                        int p = atomicAdd(&cnt[r], 1);
                        if (p < CAP) ck[r * CAP + p] = (unsigned short)(k0 + 1);
                    }
                }
            }
        }
        __syncthreads();
    }

    // exact rescore: quad of lanes per row (validated R5/R7 machinery)
    const int w    = tid >> 5;
    const int lane = tid & 31;
#pragma unroll 1
    for (int batch = 0; batch < 2; ++batch) {
        int r  = w * 16 + batch * 8 + (lane >> 2);
        int li = lane & 3;
        int n  = n0 + r;
        int c  = cnt[r];
        const float* xr = x + (size_t)n * D;
        float x2v = x2s[r];

        float bd = FLT_MAX;
        int   bk = 0x7fffffff;
        if (c <= CAP) {
            for (int jj = li; jj < c; jj += 4) {
                int k = ck[r * CAP + jj];
                float s  = seqdot256(xr, cb + (size_t)k * D);
                float dd = __fadd_rn(__fadd_rn(x2v, e2s[k]),
                                     -__fmul_rn(2.0f, s));
                if (dd < bd || (dd == bd && k < bk)) { bd = dd; bk = k; }
            }
        } else {   // overflow fallback: exact full scan
            for (int k = li; k < KCB; k += 4) {
                float s  = seqdot256(xr, cb + (size_t)k * D);
                float dd = __fadd_rn(__fadd_rn(x2v, e2s[k]),
                                     -__fmul_rn(2.0f, s));
                if (dd < bd || (dd == bd && k < bk)) { bd = dd; bk = k; }
            }
        }
#pragma unroll
        for (int m = 1; m <= 2; m <<= 1) {
            float od = __shfl_xor_sync(0xffffffffu, bd, m);
            int   ok = __shfl_xor_sync(0xffffffffu, bk, m);
            if (od < bd || (od == bd && ok < bk)) { bd = od; bk = ok; }
        }
        if (li == 0) idxs[r] = bk;
    }
    __syncthreads();

    // histogram + idx output
    if (tid < BN) {
        int k = idxs[tid];
        atomicAdd(&g_counts[k], 1u);
        if (idxf_out) idxf_out[n0 + tid] = (float)k;
    }

    // gather: y = fl(x + fl(q - x)); x re-read from gmem (exact bits)
    const float4* __restrict__ cb4 = (const float4*)cb;
    float4* y4 = (float4*)y_out;
    double acc = 0.0;
#pragma unroll 4
    for (int u = 0; u < 32; ++u) {
        int f  = tid + u * NT;
        int r  = f >> 6;
        int d4 = f & 63;
        float4 xv = __ldg(&x4[(size_t)(n0 + r) * 64 + d4]);
        int k = idxs[r];
        float4 qv = __ldg(&cb4[(size_t)k * 64 + d4]);
        float tx_ = __fadd_rn(qv.x, -xv.x);
        float ty_ = __fadd_rn(qv.y, -xv.y);
        float tz_ = __fadd_rn(qv.z, -xv.z);
        float tw_ = __fadd_rn(qv.w, -xv.w);
        float4 yv;
        yv.x = __fadd_rn(xv.x, tx_);
        yv.y = __fadd_rn(xv.y, ty_);
        yv.z = __fadd_rn(xv.z, tz_);
        yv.w = __fadd_rn(xv.w, tw_);
        y4[(size_t)(n0 + r) * 64 + d4] = yv;
        acc += (double)tx_ * tx_ + (double)ty_ * ty_ +
               (double)tz_ * tz_ + (double)tw_ * tw_;
    }

#pragma unroll
    for (int m = 16; m >= 1; m >>= 1)
        acc += __shfl_xor_sync(0xffffffffu, acc, m);
    if ((tid & 31) == 0) wsum[tid >> 5] = acc;
    __syncthreads();
    if (tid == 0) {
        double s = 0.0;
#pragma unroll
        for (int i = 0; i < 4; ++i) s += wsum[i];
        g_partial[blockIdx.x] = s;
    }
}

__global__ void __launch_bounds__(1024)
vq_finalize_kernel(float* __restrict__ scal_out, int nblocks) {
    __shared__ double redH[1024];
    __shared__ double redU[1024];
    __shared__ double redS[1024];
    int t = threadIdx.x;

    double s = 0.0;
    for (int i = t; i < nblocks; i += 1024) s += g_partial[i];

    float p    = (float)g_counts[t] * (1.0f / 65536.0f);
    float term = p * log2f(p + 1e-10f);

    redH[t] = -(double)term;
    redU[t] = (p > 0.0f) ? 1.0 : 0.0;
    redS[t] = s;
    __syncthreads();
#pragma unroll
    for (int m = 512; m >= 1; m >>= 1) {
        if (t < m) {
            redH[t] += redH[t + m];
            redU[t] += redU[t + m];
            redS[t] += redS[t + m];
        }
        __syncthreads();
    }
    if (t == 0) {
        double mse  = redS[0] / (double)((size_t)N_FIXED * D);
        float  c     = (float)mse;
        float  loss  = __fadd_rn(__fmul_rn(0.25f, c), c);
        float  H     = (float)redH[0];
        float  perp  = expf(__fmul_rn(H, 0.69314718f));
        float  usage = (float)(redU[0] / 1024.0);
        scal_out[0] = loss;
        scal_out[1] = perp;
        scal_out[2] = usage;
        scal_out[3] = H;
    }
}

extern "C" void kernel_launch(void* const* d_in, const int* in_sizes, int n_in,
                              void* d_out, int out_size) {
    (void)n_in;
    const float* x  = (const float*)d_in[0];
    const float* cb = (const float*)d_in[1];
    float* out = (float*)d_out;

    const int    n  = in_sizes[0] / D;      // 65536
    const size_t ND = (size_t)n * D;

    const long long os = (long long)out_size;
    const int with_idx  = os >= (long long)(ND + (size_t)n);
    const int with_scal = os >= (long long)(ND + (size_t)n + 4);

    cudaFuncSetAttribute(vq_main_kernel,
                         cudaFuncAttributeMaxDynamicSharedMemorySize, SMEM_B);

    vq_init_kernel<<<1, 1024>>>();
    vq_prep_kernel<<<KCB / 8, 256>>>(cb);
    vq_main_kernel<<<n / BN, NT, SMEM_B>>>(
        x, cb, out, with_idx ? (out + ND) : (float*)0);
    if (with_scal)
        vq_finalize_kernel<<<1, 1024>>>(out + ND + n, n / BN);
}

// round 12
// speedup vs baseline: 3.4927x; 3.4927x over previous
#include <cuda_runtime.h>
#include <cfloat>
#include <math.h>

// VectorQuantizer R12: R10 FFMA2 fused kernel (BN=64, NT=128, 8x8 tile,
// 2 CTAs/SM) + init fused into prep + finalize fused into last main CTA.
// Mainloop numerics byte-identical to R2/R10 (idx, y bit-exact).
// out: [ y (N*D) | idx as float (N) | loss | perplexity | usage | H ]

#define N_FIXED 65536
#define D 256
#define D4 64
#define KCB 1024
#define BN 64
#define NT 128
#define XS_STRIDE4 65
#define CS_STRIDE 132
// floats: xs 16640 | cs 8448 | e2s 1024 | idx 64 | wsum 8 | fin 768
#define SMEM_FLOATS (64 * 260 + 2 * 32 * CS_STRIDE + 1024 + 64 + 8 + 768)

__device__ float        g_e2[KCB];
__device__ unsigned int g_counts[KCB];
__device__ double       g_partial[N_FIXED / BN];
__device__ unsigned int g_done;

#define FMA2(d, a, b) \
    asm("fma.rn.f32x2 %0, %1, %2, %0;" : "+l"(d) : "l"(a), "l"(b))

__device__ __forceinline__ unsigned long long bcast2(float v) {
    unsigned long long r;
    asm("mov.b64 %0, {%1, %1};" : "=l"(r) : "f"(v));
    return r;
}

// prep: e2 per code row + zero histogram + reset done counter
__global__ void vq_prep_kernel(const float* __restrict__ cb) {
    if (blockIdx.x < 4) g_counts[blockIdx.x * 256 + threadIdx.x] = 0u;
    if (blockIdx.x == 4 && threadIdx.x == 0) g_done = 0u;

    int row  = blockIdx.x * 8 + (threadIdx.x >> 5);
    int lane = threadIdx.x & 31;
    float s = 0.0f;
#pragma unroll
    for (int j = 0; j < 8; ++j) {
        float v = cb[row * D + lane + j * 32];
        s = fmaf(v, v, s);
    }
#pragma unroll
    for (int m = 16; m >= 1; m >>= 1)
        s += __shfl_xor_sync(0xffffffffu, s, m);
    if (lane == 0) g_e2[row] = s;
}

// ---------------------------------------------------------------------------
// Fused argmin GEMM + epilogue + tail finalize. 64 rows x 1024 codes per CTA,
// 128 threads (tx16 x ty8), 8x8 FFMA2 tile, 2 CTAs/SM.
// ---------------------------------------------------------------------------
__global__ void __launch_bounds__(NT, 2)
vq_argmin_fused_kernel(const float* __restrict__ x, const float* __restrict__ cb,
                       float* __restrict__ y_out, float* __restrict__ idxf_out,
                       float* __restrict__ scal_out, int nblocks) {
    extern __shared__ float smem[];
    float*  xs    = smem;                          // 64*260
    float*  cs    = smem + 64 * 260;               // 2 * 32*CS_STRIDE
    float*  e2s   = cs + 2 * 32 * CS_STRIDE;       // 1024
    int*    idx_s = (int*)(e2s + 1024);            // 64
    double* wsum  = (double*)(idx_s + 64);         // 4 (8 floats)
    double* redH  = (double*)(idx_s + 64 + 8);     // 128
    double* redU  = redH + 128;                    // 128
    double* redS  = redU + 128;                    // 128

    const int tid = threadIdx.x;
    const int tx  = tid & 15;
    const int ty  = tid >> 4;
    const int n0  = blockIdx.x * BN;

    for (int i = tid; i < KCB; i += NT) e2s[i] = g_e2[i];

    const float4* __restrict__ x4 = (const float4*)x;
    float4* xs4 = (float4*)xs;
#pragma unroll
    for (int u = 0; u < 32; ++u) {
        int f  = tid + u * NT;
        int r  = f >> 6;
        int d4 = f & 63;
        float4 v = x4[(size_t)(n0 + r) * D4 + d4];
        xs4[r * XS_STRIDE4 + (d4 ^ ((r >> 3) & 7))] = v;
    }
    __syncthreads();

    // x2 per row (EXACT R2 chain)
    float x2r[8];
#pragma unroll
    for (int i = 0; i < 8; ++i) {
        int r  = ty * 8 + i;
        int sw = (r >> 3) & 7;
        float s = 0.0f;
#pragma unroll
        for (int q = 0; q < 4; ++q) {
            float4 v = xs4[r * XS_STRIDE4 + ((tx * 4 + q) ^ sw)];
            s = fmaf(v.x, v.x, s);
            s = fmaf(v.y, v.y, s);
            s = fmaf(v.z, v.z, s);
            s = fmaf(v.w, v.w, s);
        }
#pragma unroll
        for (int m = 8; m >= 1; m >>= 1)
            s += __shfl_xor_sync(0xffffffffu, s, m, 16);
        x2r[i] = s;
    }

    float rbd[8];
    int   rbk[8];
#pragma unroll
    for (int i = 0; i < 8; ++i) { rbd[i] = FLT_MAX; rbk[i] = 0; }

    const float4* __restrict__ cb4 = (const float4*)cb;

    // preload chunk 0 (kt=0, dt=0), transposed [dd][k]
    {
        float* dst = cs;
#pragma unroll
        for (int u = 0; u < 8; ++u) {
            int f   = tid + u * NT;
            int kl  = f >> 3;
            int dl4 = f & 7;
            float4 v = cb4[(size_t)kl * D4 + dl4];
            int ddb = dl4 * 4;
            dst[(ddb + 0) * CS_STRIDE + kl] = v.x;
            dst[(ddb + 1) * CS_STRIDE + kl] = v.y;
            dst[(ddb + 2) * CS_STRIDE + kl] = v.z;
            dst[(ddb + 3) * CS_STRIDE + kl] = v.w;
        }
    }
    __syncthreads();

    unsigned long long simp[8][4];

#pragma unroll 1
    for (int cc = 0; cc < 64; ++cc) {      // kt = cc>>3, dt = cc&7
        const int kt = cc >> 3;
        const int dt = cc & 7;

        if (dt == 0) {
#pragma unroll
            for (int i = 0; i < 8; ++i)
#pragma unroll
                for (int j = 0; j < 4; ++j) simp[i][j] = 0ull;
        }

        float4 pv[8];
        const bool have_next = (cc < 63);
        if (have_next) {
            int nkt = (cc + 1) >> 3, ndt = (cc + 1) & 7;
#pragma unroll
            for (int u = 0; u < 8; ++u) {
                int f   = tid + u * NT;
                int kl  = f >> 3;
                int dl4 = f & 7;
                pv[u] = cb4[(size_t)(nkt * 128 + kl) * D4 + ndt * 8 + dl4];
            }
        }

        const ulonglong2* csb2 =
            (const ulonglong2*)(cs + (cc & 1) * (32 * CS_STRIDE));
#pragma unroll
        for (int dd4 = 0; dd4 < 8; ++dd4) {
            float4 xv[8];
#pragma unroll
            for (int i = 0; i < 8; ++i) {
                int r = ty * 8 + i;
                xv[i] = xs4[r * XS_STRIDE4 + ((dt * 8 + dd4) ^ ((r >> 3) & 7))];
            }
#pragma unroll
            for (int t = 0; t < 4; ++t) {
                int dd = dd4 * 4 + t;
                ulonglong2 c01 = csb2[dd * 33 + tx * 2];
                ulonglong2 c23 = csb2[dd * 33 + tx * 2 + 1];
#pragma unroll
                for (int i = 0; i < 8; ++i) {
                    float xv_s = (t == 0) ? xv[i].x : (t == 1) ? xv[i].y
                               : (t == 2) ? xv[i].z : xv[i].w;
                    unsigned long long xp = bcast2(xv_s);
                    FMA2(simp[i][0], xp, c01.x);
                    FMA2(simp[i][1], xp, c01.y);
                    FMA2(simp[i][2], xp, c23.x);
                    FMA2(simp[i][3], xp, c23.y);
                }
            }
        }

        if (have_next) {
            float* dst = cs + ((cc + 1) & 1) * (32 * CS_STRIDE);
#pragma unroll
            for (int u = 0; u < 8; ++u) {
                int f   = tid + u * NT;
                int kl  = f >> 3;
                int ddb = (f & 7) * 4;
                dst[(ddb + 0) * CS_STRIDE + kl] = pv[u].x;
                dst[(ddb + 1) * CS_STRIDE + kl] = pv[u].y;
                dst[(ddb + 2) * CS_STRIDE + kl] = pv[u].z;
                dst[(ddb + 3) * CS_STRIDE + kl] = pv[u].w;
            }
        }

        // per-tile running best (k ascending, strict < keeps first)
        if (dt == 7) {
            const int kb = kt * 128 + tx * 8;
            float4 ea = *(const float4*)&e2s[kb];
            float4 eb = *(const float4*)&e2s[kb + 4];
            float e2v[8] = { ea.x, ea.y, ea.z, ea.w, eb.x, eb.y, eb.z, eb.w };
#pragma unroll
            for (int i = 0; i < 8; ++i) {
#pragma unroll
                for (int jp = 0; jp < 4; ++jp) {
                    unsigned long long s = simp[i][jp];
                    float s0 = __uint_as_float((unsigned)s);
                    float s1 = __uint_as_float((unsigned)(s >> 32));
                    int k0 = kb + jp * 2;
                    float t1 = __fadd_rn(x2r[i], e2v[jp * 2]);
                    float d0 = __fadd_rn(t1, -__fmul_rn(2.0f, s0));
                    if (d0 < rbd[i]) { rbd[i] = d0; rbk[i] = k0; }
                    float t2 = __fadd_rn(x2r[i], e2v[jp * 2 + 1]);
                    float d1 = __fadd_rn(t2, -__fmul_rn(2.0f, s1));
                    if (d1 < rbd[i]) { rbd[i] = d1; rbk[i] = k0 + 1; }
                }
            }
        }
        __syncthreads();
    }

    // final cross-lane reduction (16-lane groups), idx -> smem
#pragma unroll
    for (int i = 0; i < 8; ++i) {
        float bd = rbd[i];
        int   bk = rbk[i];
#pragma unroll
        for (int m = 1; m < 16; m <<= 1) {
            float od = __shfl_xor_sync(0xffffffffu, bd, m, 16);
            int   ok = __shfl_xor_sync(0xffffffffu, bk, m, 16);
            if (od < bd || (od == bd && ok < bk)) { bd = od; bk = ok; }
        }
        if (tx == 0) idx_s[ty * 8 + i] = bk;
    }
    __syncthreads();

    // histogram + idx output
    if (tid < BN) {
        int k = idx_s[tid];
        atomicAdd(&g_counts[k], 1u);
        if (idxf_out) idxf_out[n0 + tid] = (float)k;
    }

    // fused gather: y = fl(x + fl(q - x)); x from smem (exact bits)
    float4* y4 = (float4*)y_out;
    double acc = 0.0;
#pragma unroll 4
    for (int u = 0; u < 32; ++u) {
        int f  = tid + u * NT;
        int r  = f >> 6;
        int d4 = f & 63;
        float4 xv = xs4[r * XS_STRIDE4 + (d4 ^ ((r >> 3) & 7))];
        int k = idx_s[r];
        float4 qv = __ldg(&cb4[(size_t)k * D4 + d4]);
        float tx_ = __fadd_rn(qv.x, -xv.x);
        float ty_ = __fadd_rn(qv.y, -xv.y);
        float tz_ = __fadd_rn(qv.z, -xv.z);
        float tw_ = __fadd_rn(qv.w, -xv.w);
        float4 yv;
        yv.x = __fadd_rn(xv.x, tx_);
        yv.y = __fadd_rn(xv.y, ty_);
        yv.z = __fadd_rn(xv.z, tz_);
        yv.w = __fadd_rn(xv.w, tw_);
        y4[(size_t)(n0 + r) * D4 + d4] = yv;
        acc += (double)tx_ * tx_ + (double)ty_ * ty_ +
               (double)tz_ * tz_ + (double)tw_ * tw_;
    }

#pragma unroll
    for (int m = 16; m >= 1; m >>= 1)
        acc += __shfl_xor_sync(0xffffffffu, acc, m);
    if ((tid & 31) == 0) wsum[tid >> 5] = acc;
    __syncthreads();

    // signal completion; last CTA performs the finalize
    __shared__ unsigned int is_last;
    if (tid == 0) {
        double s = 0.0;
#pragma unroll
        for (int i = 0; i < 4; ++i) s += wsum[i];
        g_partial[blockIdx.x] = s;
        __threadfence();
        unsigned prev = atomicAdd(&g_done, 1u);
        is_last = (prev == (unsigned)(nblocks - 1)) ? 1u : 0u;
    }
    __syncthreads();

    if (is_last && scal_out) {
        __threadfence();   // acquire: all CTAs' partials/counts visible
        double sS = 0.0;
        for (int i = tid; i < nblocks; i += NT) sS += g_partial[i];
        double sH = 0.0, sU = 0.0;
#pragma unroll
        for (int j = 0; j < 8; ++j) {
            int k = tid * 8 + j;
            float p    = (float)g_counts[k] * (1.0f / 65536.0f);
            float term = p * log2f(p + 1e-10f);
            sH -= (double)term;
            sU += (p > 0.0f) ? 1.0 : 0.0;
        }
        redH[tid] = sH; redU[tid] = sU; redS[tid] = sS;
        __syncthreads();
#pragma unroll
        for (int m = 64; m >= 1; m >>= 1) {
            if (tid < m) {
                redH[tid] += redH[tid + m];
                redU[tid] += redU[tid + m];
                redS[tid] += redS[tid + m];
            }
            __syncthreads();
        }
        if (tid == 0) {
            double mse   = redS[0] / (double)((size_t)N_FIXED * D);
            float  c     = (float)mse;
            float  loss  = __fadd_rn(__fmul_rn(0.25f, c), c);
            float  H     = (float)redH[0];
            float  perp  = expf(__fmul_rn(H, 0.69314718f));
            float  usage = (float)(redU[0] / 1024.0);
            scal_out[0] = loss;
            scal_out[1] = perp;
            scal_out[2] = usage;
            scal_out[3] = H;
        }
    }
}

extern "C" void kernel_launch(void* const* d_in, const int* in_sizes, int n_in,
                              void* d_out, int out_size) {
    (void)n_in;
    const float* x  = (const float*)d_in[0];
    const float* cb = (const float*)d_in[1];
    float* out = (float*)d_out;

    const int    n  = in_sizes[0] / D;      // 65536
    const size_t ND = (size_t)n * D;

    const long long os = (long long)out_size;
    const int with_idx  = os >= (long long)(ND + (size_t)n);
    const int with_scal = os >= (long long)(ND + (size_t)n + 4);

    const size_t smem_bytes = (size_t)SMEM_FLOATS * sizeof(float);
    cudaFuncSetAttribute(vq_argmin_fused_kernel,
                         cudaFuncAttributeMaxDynamicSharedMemorySize,
                         (int)smem_bytes);

    vq_prep_kernel<<<KCB / 8, 256>>>(cb);
    vq_argmin_fused_kernel<<<n / BN, NT, smem_bytes>>>(
        x, cb, out,
        with_idx ? (out + ND) : (float*)0,
        with_scal ? (out + ND + n) : (float*)0,
        n / BN);
}

// round 13
// speedup vs baseline: 3.8583x; 1.1047x over previous
#include <cuda_runtime.h>
#include <cfloat>
#include <math.h>

// VectorQuantizer R13: R12 fused FFMA2 kernel with code staging rebuilt:
// codebook pre-transposed once to g_cbT[dim][code]; per-chunk staging is a
// contiguous cp.async copy (no in-kernel transpose, no scattered STS).
// Mainloop numerics byte-identical to R2/R10/R12 (idx, y bit-exact).
// out: [ y (N*D) | idx as float (N) | loss | perplexity | usage | H ]

#define N_FIXED 65536
#define D 256
#define D4 64
#define KCB 1024
#define BN 64
#define NT 128
#define XS_STRIDE4 65
#define CS_STRIDE 132
#define CS_BUF_BYTES (32 * CS_STRIDE * 4)   // 16896
// floats: xs 16640 | cs 8448 | e2s 1024 | idx 64 | wsum 8 | fin 768
#define SMEM_FLOATS (64 * 260 + 2 * 32 * CS_STRIDE + 1024 + 64 + 8 + 768)

__device__ float        g_e2[KCB];
__device__ float        g_cbT[D * KCB];     // [dim][code], 1 MB
__device__ unsigned int g_counts[KCB];
__device__ double       g_partial[N_FIXED / BN];
__device__ unsigned int g_done;

#define FMA2(d, a, b) \
    asm("fma.rn.f32x2 %0, %1, %2, %0;" : "+l"(d) : "l"(a), "l"(b))

__device__ __forceinline__ unsigned long long bcast2(float v) {
    unsigned long long r;
    asm("mov.b64 %0, {%1, %1};" : "=l"(r) : "f"(v));
    return r;
}
__device__ __forceinline__ unsigned int smem_u32(const void* p) {
    return (unsigned int)__cvta_generic_to_shared(p);
}
__device__ __forceinline__ void cp_async16(unsigned int dst, const void* src) {
    asm volatile("cp.async.cg.shared.global [%0], [%1], 16;"
                 :: "r"(dst), "l"(src) : "memory");
}

// prep: e2 per code row + zero histogram + reset done counter
__global__ void vq_prep_kernel(const float* __restrict__ cb) {
    if (blockIdx.x < 4) g_counts[blockIdx.x * 256 + threadIdx.x] = 0u;
    if (blockIdx.x == 4 && threadIdx.x == 0) g_done = 0u;

    int row  = blockIdx.x * 8 + (threadIdx.x >> 5);
    int lane = threadIdx.x & 31;
    float s = 0.0f;
#pragma unroll
    for (int j = 0; j < 8; ++j) {
        float v = cb[row * D + lane + j * 32];
        s = fmaf(v, v, s);
    }
#pragma unroll
    for (int m = 16; m >= 1; m >>= 1)
        s += __shfl_xor_sync(0xffffffffu, s, m);
    if (lane == 0) g_e2[row] = s;
}

// one-time codebook transpose: cb[code][dim] -> g_cbT[dim][code]
__global__ void vq_transpose_kernel(const float* __restrict__ cb) {
    __shared__ float t[32][33];
    int bx = blockIdx.x;           // code tile (32 codes)
    int by = blockIdx.y;           // dim tile (32 dims)
    int lx = threadIdx.x;          // 0..31
    int ly = threadIdx.y;          // 0..7
#pragma unroll
    for (int j = 0; j < 4; ++j)
        t[ly + j * 8][lx] = cb[(bx * 32 + ly + j * 8) * D + by * 32 + lx];
    __syncthreads();
#pragma unroll
    for (int j = 0; j < 4; ++j)
        g_cbT[(size_t)(by * 32 + ly + j * 8) * KCB + bx * 32 + lx]
            = t[lx][ly + j * 8];
}

// ---------------------------------------------------------------------------
// Fused argmin GEMM + epilogue + tail finalize. 64 rows x 1024 codes per CTA,
// 128 threads (tx16 x ty8), 8x8 FFMA2 tile, 2 CTAs/SM, cp.async staging.
// ---------------------------------------------------------------------------
__global__ void __launch_bounds__(NT, 2)
vq_argmin_fused_kernel(const float* __restrict__ x, const float* __restrict__ cb,
                       float* __restrict__ y_out, float* __restrict__ idxf_out,
                       float* __restrict__ scal_out, int nblocks) {
    extern __shared__ float smem[];
    float*  xs    = smem;                          // 64*260
    float*  cs    = smem + 64 * 260;               // 2 * 32*CS_STRIDE
    float*  e2s   = cs + 2 * 32 * CS_STRIDE;       // 1024
    int*    idx_s = (int*)(e2s + 1024);            // 64
    double* wsum  = (double*)(idx_s + 64);         // 4 (8 floats)
    double* redH  = (double*)(idx_s + 64 + 8);     // 128
    double* redU  = redH + 128;                    // 128
    double* redS  = redU + 128;                    // 128

    const int tid = threadIdx.x;
    const int tx  = tid & 15;
    const int ty  = tid >> 4;
    const int n0  = blockIdx.x * BN;
    const unsigned int cs_sm = smem_u32(cs);

    // preload code chunk 0 (kt=0, dt=0) via cp.async: contiguous copy
    {
#pragma unroll
        for (int u = 0; u < 8; ++u) {
            int f   = tid + u * NT;        // 0..1023
            int dd  = f >> 5;              // 0..31
            int seg = f & 31;              // 16B segment in 512B row
            cp_async16(cs_sm + dd * (CS_STRIDE * 4) + seg * 16,
                       g_cbT + (size_t)dd * KCB + seg * 4);
        }
        asm volatile("cp.async.commit_group;" ::: "memory");
    }

    for (int i = tid; i < KCB; i += NT) e2s[i] = g_e2[i];

    const float4* __restrict__ x4 = (const float4*)x;
    float4* xs4 = (float4*)xs;
#pragma unroll
    for (int u = 0; u < 32; ++u) {
        int f  = tid + u * NT;
        int r  = f >> 6;
        int d4 = f & 63;
        float4 v = x4[(size_t)(n0 + r) * D4 + d4];
        xs4[r * XS_STRIDE4 + (d4 ^ ((r >> 3) & 7))] = v;
    }
    __syncthreads();

    // x2 per row (EXACT R2 chain)
    float x2r[8];
#pragma unroll
    for (int i = 0; i < 8; ++i) {
        int r  = ty * 8 + i;
        int sw = (r >> 3) & 7;
        float s = 0.0f;
#pragma unroll
        for (int q = 0; q < 4; ++q) {
            float4 v = xs4[r * XS_STRIDE4 + ((tx * 4 + q) ^ sw)];
            s = fmaf(v.x, v.x, s);
            s = fmaf(v.y, v.y, s);
            s = fmaf(v.z, v.z, s);
            s = fmaf(v.w, v.w, s);
        }
#pragma unroll
        for (int m = 8; m >= 1; m >>= 1)
            s += __shfl_xor_sync(0xffffffffu, s, m, 16);
        x2r[i] = s;
    }

    float rbd[8];
    int   rbk[8];
#pragma unroll
    for (int i = 0; i < 8; ++i) { rbd[i] = FLT_MAX; rbk[i] = 0; }

    const float4* __restrict__ cb4 = (const float4*)cb;

    // chunk 0 staged
    asm volatile("cp.async.wait_group 0;" ::: "memory");
    __syncthreads();

    unsigned long long simp[8][4];

#pragma unroll 1
    for (int cc = 0; cc < 64; ++cc) {      // kt = cc>>3, dt = cc&7
        const int kt = cc >> 3;
        const int dt = cc & 7;

        if (dt == 0) {
#pragma unroll
            for (int i = 0; i < 8; ++i)
#pragma unroll
                for (int j = 0; j < 4; ++j) simp[i][j] = 0ull;
        }

        // async prefetch of next chunk into the other buffer
        const bool have_next = (cc < 63);
        if (have_next) {
            int nkt = (cc + 1) >> 3, ndt = (cc + 1) & 7;
            unsigned int dstb = cs_sm + (((cc + 1) & 1) ? CS_BUF_BYTES : 0);
#pragma unroll
            for (int u = 0; u < 8; ++u) {
                int f   = tid + u * NT;
                int dd  = f >> 5;
                int seg = f & 31;
                cp_async16(dstb + dd * (CS_STRIDE * 4) + seg * 16,
                           g_cbT + (size_t)(ndt * 32 + dd) * KCB
                                 + nkt * 128 + seg * 4);
            }
            asm volatile("cp.async.commit_group;" ::: "memory");
        }

        const ulonglong2* csb2 =
            (const ulonglong2*)(cs + (cc & 1) * (32 * CS_STRIDE));
#pragma unroll
        for (int dd4 = 0; dd4 < 8; ++dd4) {
            float4 xv[8];
#pragma unroll
            for (int i = 0; i < 8; ++i) {
                int r = ty * 8 + i;
                xv[i] = xs4[r * XS_STRIDE4 + ((dt * 8 + dd4) ^ ((r >> 3) & 7))];
            }
#pragma unroll
            for (int t = 0; t < 4; ++t) {
                int dd = dd4 * 4 + t;
                ulonglong2 c01 = csb2[dd * 33 + tx * 2];
                ulonglong2 c23 = csb2[dd * 33 + tx * 2 + 1];
#pragma unroll
                for (int i = 0; i < 8; ++i) {
                    float xv_s = (t == 0) ? xv[i].x : (t == 1) ? xv[i].y
                               : (t == 2) ? xv[i].z : xv[i].w;
                    unsigned long long xp = bcast2(xv_s);
                    FMA2(simp[i][0], xp, c01.x);
                    FMA2(simp[i][1], xp, c01.y);
                    FMA2(simp[i][2], xp, c23.x);
                    FMA2(simp[i][3], xp, c23.y);
                }
            }
        }

        // per-tile running best (k ascending, strict < keeps first)
        if (dt == 7) {
            const int kb = kt * 128 + tx * 8;
            float4 ea = *(const float4*)&e2s[kb];
            float4 eb = *(const float4*)&e2s[kb + 4];
            float e2v[8] = { ea.x, ea.y, ea.z, ea.w, eb.x, eb.y, eb.z, eb.w };
#pragma unroll
            for (int i = 0; i < 8; ++i) {
#pragma unroll
                for (int jp = 0; jp < 4; ++jp) {
                    unsigned long long s = simp[i][jp];
                    float s0 = __uint_as_float((unsigned)s);
                    float s1 = __uint_as_float((unsigned)(s >> 32));
                    int k0 = kb + jp * 2;
                    float t1 = __fadd_rn(x2r[i], e2v[jp * 2]);
                    float d0 = __fadd_rn(t1, -__fmul_rn(2.0f, s0));
                    if (d0 < rbd[i]) { rbd[i] = d0; rbk[i] = k0; }
                    float t2 = __fadd_rn(x2r[i], e2v[jp * 2 + 1]);
                    float d1 = __fadd_rn(t2, -__fmul_rn(2.0f, s1));
                    if (d1 < rbd[i]) { rbd[i] = d1; rbk[i] = k0 + 1; }
                }
            }
        }

        if (have_next)
            asm volatile("cp.async.wait_group 0;" ::: "memory");
        __syncthreads();
    }

    // final cross-lane reduction (16-lane groups), idx -> smem
#pragma unroll
    for (int i = 0; i < 8; ++i) {
        float bd = rbd[i];
        int   bk = rbk[i];
#pragma unroll
        for (int m = 1; m < 16; m <<= 1) {
            float od = __shfl_xor_sync(0xffffffffu, bd, m, 16);
            int   ok = __shfl_xor_sync(0xffffffffu, bk, m, 16);
            if (od < bd || (od == bd && ok < bk)) { bd = od; bk = ok; }
        }
        if (tx == 0) idx_s[ty * 8 + i] = bk;
    }
    __syncthreads();

    // histogram + idx output
    if (tid < BN) {
        int k = idx_s[tid];
        atomicAdd(&g_counts[k], 1u);
        if (idxf_out) idxf_out[n0 + tid] = (float)k;
    }

    // fused gather: y = fl(x + fl(q - x)); x from smem (exact bits)
    float4* y4 = (float4*)y_out;
    double acc = 0.0;
#pragma unroll 4
    for (int u = 0; u < 32; ++u) {
        int f  = tid + u * NT;
        int r  = f >> 6;
        int d4 = f & 63;
        float4 xv = xs4[r * XS_STRIDE4 + (d4 ^ ((r >> 3) & 7))];
        int k = idx_s[r];
        float4 qv = __ldg(&cb4[(size_t)k * D4 + d4]);
        float tx_ = __fadd_rn(qv.x, -xv.x);
        float ty_ = __fadd_rn(qv.y, -xv.y);
        float tz_ = __fadd_rn(qv.z, -xv.z);
        float tw_ = __fadd_rn(qv.w, -xv.w);
        float4 yv;
        yv.x = __fadd_rn(xv.x, tx_);
        yv.y = __fadd_rn(xv.y, ty_);
        yv.z = __fadd_rn(xv.z, tz_);
        yv.w = __fadd_rn(xv.w, tw_);
        y4[(size_t)(n0 + r) * D4 + d4] = yv;
        acc += (double)tx_ * tx_ + (double)ty_ * ty_ +
               (double)tz_ * tz_ + (double)tw_ * tw_;
    }

#pragma unroll
    for (int m = 16; m >= 1; m >>= 1)
        acc += __shfl_xor_sync(0xffffffffu, acc, m);
    if ((tid & 31) == 0) wsum[tid >> 5] = acc;
    __syncthreads();

    // signal completion; last CTA performs the finalize
    __shared__ unsigned int is_last;
    if (tid == 0) {
        double s = 0.0;
#pragma unroll
        for (int i = 0; i < 4; ++i) s += wsum[i];
        g_partial[blockIdx.x] = s;
        __threadfence();
        unsigned prev = atomicAdd(&g_done, 1u);
        is_last = (prev == (unsigned)(nblocks - 1)) ? 1u : 0u;
    }
    __syncthreads();

    if (is_last && scal_out) {
        __threadfence();
        double sS = 0.0;
        for (int i = tid; i < nblocks; i += NT) sS += g_partial[i];
        double sH = 0.0, sU = 0.0;
#pragma unroll
        for (int j = 0; j < 8; ++j) {
            int k = tid * 8 + j;
            float p    = (float)g_counts[k] * (1.0f / 65536.0f);
            float term = p * log2f(p + 1e-10f);
            sH -= (double)term;
            sU += (p > 0.0f) ? 1.0 : 0.0;
        }
        redH[tid] = sH; redU[tid] = sU; redS[tid] = sS;
        __syncthreads();
#pragma unroll
        for (int m = 64; m >= 1; m >>= 1) {
            if (tid < m) {
                redH[tid] += redH[tid + m];
                redU[tid] += redU[tid + m];
                redS[tid] += redS[tid + m];
            }
            __syncthreads();
        }
        if (tid == 0) {
            double mse   = redS[0] / (double)((size_t)N_FIXED * D);
            float  c     = (float)mse;
            float  loss  = __fadd_rn(__fmul_rn(0.25f, c), c);
            float  H     = (float)redH[0];
            float  perp  = expf(__fmul_rn(H, 0.69314718f));
            float  usage = (float)(redU[0] / 1024.0);
            scal_out[0] = loss;
            scal_out[1] = perp;
            scal_out[2] = usage;
            scal_out[3] = H;
        }
    }
}

extern "C" void kernel_launch(void* const* d_in, const int* in_sizes, int n_in,
                              void* d_out, int out_size) {
    (void)n_in;
    const float* x  = (const float*)d_in[0];
    const float* cb = (const float*)d_in[1];
    float* out = (float*)d_out;

    const int    n  = in_sizes[0] / D;      // 65536
    const size_t ND = (size_t)n * D;

    const long long os = (long long)out_size;
    const int with_idx  = os >= (long long)(ND + (size_t)n);
    const int with_scal = os >= (long long)(ND + (size_t)n + 4);

    const size_t smem_bytes = (size_t)SMEM_FLOATS * sizeof(float);
    cudaFuncSetAttribute(vq_argmin_fused_kernel,
                         cudaFuncAttributeMaxDynamicSharedMemorySize,
                         (int)smem_bytes);

    vq_prep_kernel<<<KCB / 8, 256>>>(cb);
    dim3 tgrid(KCB / 32, D / 32);
    dim3 tblk(32, 8);
    vq_transpose_kernel<<<tgrid, tblk>>>(cb);
    vq_argmin_fused_kernel<<<n / BN, NT, smem_bytes>>>(
        x, cb, out,
        with_idx ? (out + ND) : (float*)0,
        with_scal ? (out + ND + n) : (float*)0,
        n / BN);
}

// round 14
// speedup vs baseline: 3.8879x; 1.0077x over previous
#include <cuda_runtime.h>
#include <cfloat>
#include <math.h>

// VectorQuantizer R14 (convergence): R13 fused FFMA2 kernel at the rt=3
// register-bank floor; prep+transpose fused to one launch; x tile staged
// via cp.async. Mainloop numerics byte-identical to R2/R10/R13.
// out: [ y (N*D) | idx as float (N) | loss | perplexity | usage | H ]

#define N_FIXED 65536
#define D 256
#define D4 64
#define KCB 1024
#define BN 64
#define NT 128
#define XS_STRIDE4 65
#define CS_STRIDE 132
#define CS_BUF_BYTES (32 * CS_STRIDE * 4)
#define SMEM_FLOATS (64 * 260 + 2 * 32 * CS_STRIDE + 1024 + 64 + 8 + 768)

__device__ float        g_e2[KCB];
__device__ float        g_cbT[D * KCB];     // [dim][code]
__device__ unsigned int g_counts[KCB];
__device__ double       g_partial[N_FIXED / BN];
__device__ unsigned int g_done;

#define FMA2(d, a, b) \
    asm("fma.rn.f32x2 %0, %1, %2, %0;" : "+l"(d) : "l"(a), "l"(b))

__device__ __forceinline__ unsigned long long bcast2(float v) {
    unsigned long long r;
    asm("mov.b64 %0, {%1, %1};" : "=l"(r) : "f"(v));
    return r;
}
__device__ __forceinline__ unsigned int smem_u32(const void* p) {
    return (unsigned int)__cvta_generic_to_shared(p);
}
__device__ __forceinline__ void cp_async16(unsigned int dst, const void* src) {
    asm volatile("cp.async.cg.shared.global [%0], [%1], 16;"
                 :: "r"(dst), "l"(src) : "memory");
}

// ---------------------------------------------------------------------------
// prep: e2 per code row (exact chain) + histogram/done reset + codebook
// transpose tile (32 codes x 64 dims per block; 128 blocks cover 1024x256).
// ---------------------------------------------------------------------------
__global__ void __launch_bounds__(256)
vq_prep_kernel(const float* __restrict__ cb) {
    __shared__ float t[32][65];
    const int bx  = blockIdx.x;
    const int tid = threadIdx.x;

    if (bx < 4) g_counts[bx * 256 + tid] = 0u;
    if (bx == 4 && tid == 0) g_done = 0u;

    // e2 (bit-exact chain, same as all prior rounds)
    {
        int row  = bx * 8 + (tid >> 5);
        int lane = tid & 31;
        float s = 0.0f;
#pragma unroll
        for (int j = 0; j < 8; ++j) {
            float v = cb[row * D + lane + j * 32];
            s = fmaf(v, v, s);
        }
#pragma unroll
        for (int m = 16; m >= 1; m >>= 1)
            s += __shfl_xor_sync(0xffffffffu, s, m);
        if (lane == 0) g_e2[row] = s;
    }

    // transpose tile: codes ci*32..+31, dims di*64..+63
    const int ci = bx & 31;
    const int di = bx >> 5;
    {
        int lx = tid & 63;         // dim within tile
        int ly = tid >> 6;         // 0..3
#pragma unroll
        for (int j = 0; j < 8; ++j)
            t[ly + j * 4][lx] = cb[(ci * 32 + ly + j * 4) * D + di * 64 + lx];
    }
    __syncthreads();
    {
        int lx = tid & 31;         // code within tile
        int ly = tid >> 5;         // 0..7
#pragma unroll
        for (int j = 0; j < 8; ++j)
            g_cbT[(size_t)(di * 64 + ly + j * 8) * KCB + ci * 32 + lx]
                = t[lx][ly + j * 8];
    }
}

// ---------------------------------------------------------------------------
// Fused argmin GEMM + epilogue + tail finalize. 64 rows x 1024 codes per CTA,
// 128 threads (tx16 x ty8), 8x8 FFMA2 tile, 2 CTAs/SM, cp.async staging.
// ---------------------------------------------------------------------------
__global__ void __launch_bounds__(NT, 2)
vq_argmin_fused_kernel(const float* __restrict__ x, const float* __restrict__ cb,
                       float* __restrict__ y_out, float* __restrict__ idxf_out,
                       float* __restrict__ scal_out, int nblocks) {
    extern __shared__ float smem[];
    float*  xs    = smem;                          // 64*260
    float*  cs    = smem + 64 * 260;               // 2 * 32*CS_STRIDE
    float*  e2s   = cs + 2 * 32 * CS_STRIDE;       // 1024
    int*    idx_s = (int*)(e2s + 1024);            // 64
    double* wsum  = (double*)(idx_s + 64);         // 4
    double* redH  = (double*)(idx_s + 64 + 8);     // 128
    double* redU  = redH + 128;                    // 128
    double* redS  = redU + 128;                    // 128

    const int tid = threadIdx.x;
    const int tx  = tid & 15;
    const int ty  = tid >> 4;
    const int n0  = blockIdx.x * BN;
    const unsigned int cs_sm = smem_u32(cs);
    const unsigned int xs_sm = smem_u32(xs);

    // chunk 0 staging (contiguous rows of g_cbT)
#pragma unroll
    for (int u = 0; u < 8; ++u) {
        int f   = tid + u * NT;
        int dd  = f >> 5;
        int seg = f & 31;
        cp_async16(cs_sm + dd * (CS_STRIDE * 4) + seg * 16,
                   g_cbT + (size_t)dd * KCB + seg * 4);
    }
    // x tile staging, swizzled dst (same layout as before)
#pragma unroll
    for (int u = 0; u < 32; ++u) {
        int f  = tid + u * NT;
        int r  = f >> 6;
        int d4 = f & 63;
        cp_async16(xs_sm + (r * XS_STRIDE4 + (d4 ^ ((r >> 3) & 7))) * 16,
                   x + (size_t)(n0 + r) * D + d4 * 4);
    }
    asm volatile("cp.async.commit_group;" ::: "memory");

    for (int i = tid; i < KCB; i += NT) e2s[i] = g_e2[i];

    asm volatile("cp.async.wait_group 0;" ::: "memory");
    __syncthreads();

    const float4* xs4 = (const float4*)xs;

    // x2 per row (EXACT R2 chain)
    float x2r[8];
#pragma unroll
    for (int i = 0; i < 8; ++i) {
        int r  = ty * 8 + i;
        int sw = (r >> 3) & 7;
        float s = 0.0f;
#pragma unroll
        for (int q = 0; q < 4; ++q) {
            float4 v = xs4[r * XS_STRIDE4 + ((tx * 4 + q) ^ sw)];
            s = fmaf(v.x, v.x, s);
            s = fmaf(v.y, v.y, s);
            s = fmaf(v.z, v.z, s);
            s = fmaf(v.w, v.w, s);
        }
#pragma unroll
        for (int m = 8; m >= 1; m >>= 1)
            s += __shfl_xor_sync(0xffffffffu, s, m, 16);
        x2r[i] = s;
    }

    float rbd[8];
    int   rbk[8];
#pragma unroll
    for (int i = 0; i < 8; ++i) { rbd[i] = FLT_MAX; rbk[i] = 0; }

    const float4* __restrict__ cb4 = (const float4*)cb;

    unsigned long long simp[8][4];

#pragma unroll 1
    for (int cc = 0; cc < 64; ++cc) {      // kt = cc>>3, dt = cc&7
        const int kt = cc >> 3;
        const int dt = cc & 7;

        if (dt == 0) {
#pragma unroll
            for (int i = 0; i < 8; ++i)
#pragma unroll
                for (int j = 0; j < 4; ++j) simp[i][j] = 0ull;
        }

        // async prefetch of next chunk into the other buffer
        const bool have_next = (cc < 63);
        if (have_next) {
            int nkt = (cc + 1) >> 3, ndt = (cc + 1) & 7;
            unsigned int dstb = cs_sm + (((cc + 1) & 1) ? CS_BUF_BYTES : 0);
#pragma unroll
            for (int u = 0; u < 8; ++u) {
                int f   = tid + u * NT;
                int dd  = f >> 5;
                int seg = f & 31;
                cp_async16(dstb + dd * (CS_STRIDE * 4) + seg * 16,
                           g_cbT + (size_t)(ndt * 32 + dd) * KCB
                                 + nkt * 128 + seg * 4);
            }
            asm volatile("cp.async.commit_group;" ::: "memory");
        }

        const ulonglong2* csb2 =
            (const ulonglong2*)(cs + (cc & 1) * (32 * CS_STRIDE));
#pragma unroll
        for (int dd4 = 0; dd4 < 8; ++dd4) {
            float4 xv[8];
#pragma unroll
            for (int i = 0; i < 8; ++i) {
                int r = ty * 8 + i;
                xv[i] = xs4[r * XS_STRIDE4 + ((dt * 8 + dd4) ^ ((r >> 3) & 7))];
            }
#pragma unroll
            for (int t = 0; t < 4; ++t) {
                int dd = dd4 * 4 + t;
                ulonglong2 c01 = csb2[dd * 33 + tx * 2];
                ulonglong2 c23 = csb2[dd * 33 + tx * 2 + 1];
#pragma unroll
                for (int i = 0; i < 8; ++i) {
                    float xv_s = (t == 0) ? xv[i].x : (t == 1) ? xv[i].y
                               : (t == 2) ? xv[i].z : xv[i].w;
                    unsigned long long xp = bcast2(xv_s);
                    FMA2(simp[i][0], xp, c01.x);
                    FMA2(simp[i][1], xp, c01.y);
                    FMA2(simp[i][2], xp, c23.x);
                    FMA2(simp[i][3], xp, c23.y);
                }
            }
        }

        // per-tile running best (k ascending, strict < keeps first)
        if (dt == 7) {
            const int kb = kt * 128 + tx * 8;
            float4 ea = *(const float4*)&e2s[kb];
            float4 eb = *(const float4*)&e2s[kb + 4];
            float e2v[8] = { ea.x, ea.y, ea.z, ea.w, eb.x, eb.y, eb.z, eb.w };
#pragma unroll
            for (int i = 0; i < 8; ++i) {
#pragma unroll
                for (int jp = 0; jp < 4; ++jp) {
                    unsigned long long s = simp[i][jp];
                    float s0 = __uint_as_float((unsigned)s);
                    float s1 = __uint_as_float((unsigned)(s >> 32));
                    int k0 = kb + jp * 2;
                    float t1 = __fadd_rn(x2r[i], e2v[jp * 2]);
                    float d0 = __fadd_rn(t1, -__fmul_rn(2.0f, s0));
                    if (d0 < rbd[i]) { rbd[i] = d0; rbk[i] = k0; }
                    float t2 = __fadd_rn(x2r[i], e2v[jp * 2 + 1]);
                    float d1 = __fadd_rn(t2, -__fmul_rn(2.0f, s1));
                    if (d1 < rbd[i]) { rbd[i] = d1; rbk[i] = k0 + 1; }
                }
            }
        }

        if (have_next)
            asm volatile("cp.async.wait_group 0;" ::: "memory");
        __syncthreads();
    }

    // final cross-lane reduction (16-lane groups), idx -> smem
#pragma unroll
    for (int i = 0; i < 8; ++i) {
        float bd = rbd[i];
        int   bk = rbk[i];
#pragma unroll
        for (int m = 1; m < 16; m <<= 1) {
            float od = __shfl_xor_sync(0xffffffffu, bd, m, 16);
            int   ok = __shfl_xor_sync(0xffffffffu, bk, m, 16);
            if (od < bd || (od == bd && ok < bk)) { bd = od; bk = ok; }
        }
        if (tx == 0) idx_s[ty * 8 + i] = bk;
    }
    __syncthreads();

    // histogram + idx output
    if (tid < BN) {
        int k = idx_s[tid];
        atomicAdd(&g_counts[k], 1u);
        if (idxf_out) idxf_out[n0 + tid] = (float)k;
    }

    // fused gather: y = fl(x + fl(q - x)); x from smem (exact bits)
    float4* y4 = (float4*)y_out;
    double acc = 0.0;
#pragma unroll 4
    for (int u = 0; u < 32; ++u) {
        int f  = tid + u * NT;
        int r  = f >> 6;
        int d4 = f & 63;
        float4 xv = xs4[r * XS_STRIDE4 + (d4 ^ ((r >> 3) & 7))];
        int k = idx_s[r];
        float4 qv = __ldg(&cb4[(size_t)k * D4 + d4]);
        float tx_ = __fadd_rn(qv.x, -xv.x);
        float ty_ = __fadd_rn(qv.y, -xv.y);
        float tz_ = __fadd_rn(qv.z, -xv.z);
        float tw_ = __fadd_rn(qv.w, -xv.w);
        float4 yv;
        yv.x = __fadd_rn(xv.x, tx_);
        yv.y = __fadd_rn(xv.y, ty_);
        yv.z = __fadd_rn(xv.z, tz_);
        yv.w = __fadd_rn(xv.w, tw_);
        y4[(size_t)(n0 + r) * D4 + d4] = yv;
        acc += (double)tx_ * tx_ + (double)ty_ * ty_ +
               (double)tz_ * tz_ + (double)tw_ * tw_;
    }

#pragma unroll
    for (int m = 16; m >= 1; m >>= 1)
        acc += __shfl_xor_sync(0xffffffffu, acc, m);
    if ((tid & 31) == 0) wsum[tid >> 5] = acc;
    __syncthreads();

    // signal completion; last CTA performs the finalize
    __shared__ unsigned int is_last;
    if (tid == 0) {
        double s = 0.0;
#pragma unroll
        for (int i = 0; i < 4; ++i) s += wsum[i];
        g_partial[blockIdx.x] = s;
        __threadfence();
        unsigned prev = atomicAdd(&g_done, 1u);
        is_last = (prev == (unsigned)(nblocks - 1)) ? 1u : 0u;
    }
    __syncthreads();

    if (is_last && scal_out) {
        __threadfence();
        double sS = 0.0;
        for (int i = tid; i < nblocks; i += NT) sS += g_partial[i];
        double sH = 0.0, sU = 0.0;
#pragma unroll
        for (int j = 0; j < 8; ++j) {
            int k = tid * 8 + j;
            float p    = (float)g_counts[k] * (1.0f / 65536.0f);
            float term = p * log2f(p + 1e-10f);
            sH -= (double)term;
            sU += (p > 0.0f) ? 1.0 : 0.0;
        }
        redH[tid] = sH; redU[tid] = sU; redS[tid] = sS;
        __syncthreads();
#pragma unroll
        for (int m = 64; m >= 1; m >>= 1) {
            if (tid < m) {
                redH[tid] += redH[tid + m];
                redU[tid] += redU[tid + m];
                redS[tid] += redS[tid + m];
            }
            __syncthreads();
        }
        if (tid == 0) {
            double mse   = redS[0] / (double)((size_t)N_FIXED * D);
            float  c     = (float)mse;
            float  loss  = __fadd_rn(__fmul_rn(0.25f, c), c);
            float  H     = (float)redH[0];
            float  perp  = expf(__fmul_rn(H, 0.69314718f));
            float  usage = (float)(redU[0] / 1024.0);
            scal_out[0] = loss;
            scal_out[1] = perp;
            scal_out[2] = usage;
            scal_out[3] = H;
        }
    }
}

extern "C" void kernel_launch(void* const* d_in, const int* in_sizes, int n_in,
                              void* d_out, int out_size) {
    (void)n_in;
    const float* x  = (const float*)d_in[0];
    const float* cb = (const float*)d_in[1];
    float* out = (float*)d_out;

    const int    n  = in_sizes[0] / D;      // 65536
    const size_t ND = (size_t)n * D;

    const long long os = (long long)out_size;
    const int with_idx  = os >= (long long)(ND + (size_t)n);
    const int with_scal = os >= (long long)(ND + (size_t)n + 4);

    const size_t smem_bytes = (size_t)SMEM_FLOATS * sizeof(float);
    cudaFuncSetAttribute(vq_argmin_fused_kernel,
                         cudaFuncAttributeMaxDynamicSharedMemorySize,
                         (int)smem_bytes);

    vq_prep_kernel<<<KCB / 8, 256>>>(cb);
    vq_argmin_fused_kernel<<<n / BN, NT, smem_bytes>>>(
        x, cb, out,
        with_idx ? (out + ND) : (float*)0,
        with_scal ? (out + ND + n) : (float*)0,
        n / BN);
}